// round 14
// baseline (speedup 1.0000x reference)
#include <cuda_runtime.h>
#include <cstdint>

// TropicalLinear forward on GB300:
//   out[n,o] = max_i( x[n,i] + w[o,i] ) + bias[o]
//
// R13: R12 (intra-warp k-split, shfl-max epilogue, no scratch/barrier) with
//      4 n-rows per thread (I=4): smem crossbar traffic 2.5 -> 1.5 B/pair
//      (w rows amortized over 4 n's). L1 was 63% in R12 == binding resource.
//   - __launch_bounds__(256,3): 84 regs -> acc[4][8] + front-batched 12-LDS
//     MLP per stage (R12's 64-reg cap starved load batching).
//   - warp tile 4n x 8o, CTA 8 warps = 8n x 32o, grid 32x16 = 512 CTAs.
//   - natural row-major smem, bank-clean LDS.128 everywhere, 20 KB static.

#define N_ROWS  128
#define IN_DIM  1024
#define OUT_DIM 1024
#define KC      128                 // k per smem stage
#define NSTAGE  (IN_DIM / KC)       // 8
#define TN      8                   // CTA n-tile
#define TO      32                  // CTA o-tile

__device__ __forceinline__ float neg_inf() { return __int_as_float(0xff800000); }

__device__ __forceinline__ unsigned long long add2(unsigned long long a,
                                                   unsigned long long b) {
    unsigned long long r;
    asm("add.rn.f32x2 %0, %1, %2;" : "=l"(r) : "l"(a), "l"(b));
    return r;
}
__device__ __forceinline__ float lo32(unsigned long long v) {
    return __uint_as_float((unsigned int)v);
}
__device__ __forceinline__ float hi32(unsigned long long v) {
    return __uint_as_float((unsigned int)(v >> 32));
}

extern "C" __global__ void __launch_bounds__(256, 3)
tropical_kernel(const float* __restrict__ x,
                const float* __restrict__ w,
                const float* __restrict__ bias,
                float* __restrict__ out)
{
    // natural row-major tiles, float4 granular: 4 KB + 16 KB = 20 KB static
    __shared__ float4 xs4[TN * (KC / 4)];   // [8 rows][32 float4]
    __shared__ float4 ws4[TO * (KC / 4)];   // [32 rows][32 float4]

    const int tid  = threadIdx.x;
    const int lane = tid & 31;
    const int wid  = tid >> 5;          // 0..7
    const int wn   = wid >> 2;          // 0..1 -> n rows {4wn .. 4wn+3}
    const int wo   = wid & 3;           // 0..3 -> o rows {8wo .. 8wo+7}

    const int o0 = blockIdx.x * TO;     // 32 o-tiles
    const int n0 = blockIdx.y * TN;     // 16 n-tiles

    // staging coordinates (row-coalesced: one 512B row-chunk per warp)
    const int srow = tid >> 5;          // 0..7
    const int sc   = tid & 31;          // float4 within row

    float acc[4][8];
#pragma unroll
    for (int i = 0; i < 4; ++i)
#pragma unroll
        for (int j = 0; j < 8; ++j)
            acc[i][j] = neg_inf();

#pragma unroll 1
    for (int s = 0; s < NSTAGE; ++s) {
        const int k0 = s * KC;

        // ---- stage (coalesced LDG.128 -> linear STS.128, conflict-free) ----
        xs4[srow * 32 + sc] =
            *(const float4*)(x + (size_t)(n0 + srow) * IN_DIM + k0 + sc * 4);
#pragma unroll
        for (int it = 0; it < 4; ++it) {
            const int r = srow + it * 8;
            ws4[r * 32 + sc] =
                *(const float4*)(w + (size_t)(o0 + r) * IN_DIM + k0 + sc * 4);
        }
        __syncthreads();

        // ---- compute: lane handles k = k0 + 4*lane .. +3 (disjoint slices) ----
        // all LDS.128 lane-stride 4 floats -> bank-clean
        ulonglong2 xv[4];
#pragma unroll
        for (int i = 0; i < 4; ++i)
            xv[i] = *(const ulonglong2*)&xs4[(4 * wn + i) * 32 + lane];

#pragma unroll
        for (int h = 0; h < 2; ++h) {               // w in halves of 4 o-rows
            ulonglong2 wv[4];
#pragma unroll
            for (int j = 0; j < 4; ++j)
                wv[j] = *(const ulonglong2*)&ws4[(8 * wo + h * 4 + j) * 32 + lane];
#pragma unroll
            for (int i = 0; i < 4; ++i) {
#pragma unroll
                for (int j = 0; j < 4; ++j) {
                    unsigned long long s0 = add2(xv[i].x, wv[j].x);  // k0..k1
                    unsigned long long s1 = add2(xv[i].y, wv[j].y);  // k2..k3
                    float t0 = fmaxf(lo32(s0), hi32(s0));
                    float t1 = fmaxf(lo32(s1), hi32(s1));
                    acc[i][h * 4 + j] = fmaxf(acc[i][h * 4 + j], fmaxf(t0, t1));
                }
            }
        }
        __syncthreads();
    }

    // ---- butterfly shfl-max across lanes (k-slices) ----
#pragma unroll
    for (int i = 0; i < 4; ++i)
#pragma unroll
        for (int j = 0; j < 8; ++j) {
#pragma unroll
            for (int m = 16; m >= 1; m >>= 1)
                acc[i][j] = fmaxf(acc[i][j],
                                  __shfl_xor_sync(0xffffffffu, acc[i][j], m));
        }

    // ---- write: each lane emits exactly one (i,j) output ----
    const int li = lane >> 3;           // 0..3
    const int lj = lane & 7;            // 0..7
    float v = neg_inf();
#pragma unroll
    for (int i = 0; i < 4; ++i)
#pragma unroll
        for (int j = 0; j < 8; ++j)
            if (li == i && lj == j) v = acc[i][j];

    {
        const int n = n0 + 4 * wn + li;
        const int o = o0 + 8 * wo + lj;
        out[(size_t)n * OUT_DIM + o] = v + __ldg(&bias[o]);
    }
}

extern "C" void kernel_launch(void* const* d_in, const int* in_sizes, int n_in,
                              void* d_out, int out_size)
{
    const float* x    = (const float*)d_in[0];   // [128, 1024]
    const float* w    = (const float*)d_in[1];   // [1024, 1024]
    const float* bias = (const float*)d_in[2];   // [1024]
    float* out = (float*)d_out;                  // [128, 1024]

    dim3 grid(OUT_DIM / TO, N_ROWS / TN);        // (32, 16) = 512 CTAs
    tropical_kernel<<<grid, 256>>>(x, w, bias, out);
}